// round 13
// baseline (speedup 1.0000x reference)
#include <cuda_runtime.h>
#include <cuda_fp16.h>

#define LDIM 80
#define RDIM 80
#define BATCH 128
#define UD 128
#define CD 32
#define DD 416
#define NDIAG 159
#define KB16 26          // 416 / 16
#define KBW 28           // padded for prefetch
#define QWH (2 * KB16 * 32 * 4)   // uint words per 32x416 fp16 fragment tile
#define NTASK 25600               // sum over d of 4*nc

// Fragment-packed fp16 h per (l, r, qb): [2 mb][8 kb][32 lanes] uint4 = 8 KB slab.
__device__ unsigned g_hhalf[LDIM][RDIM][4][2 * 8 * 32 * 4];   // ~105 MB
// fp16 inputs, (l, r, b, c) layout.
__device__ __half   g_sTh[LDIM][RDIM][BATCH][CD];             // ~52 MB
// Fragment-packed fp16 weights: jblk 0..47 Wr; 48..111 Wz interleaved; 112..127 [WU|Wij]
__device__ uint2    g_wph[128][KBW][32];
// Dataflow flags + ticket.
__device__ unsigned g_hflag[LDIM][RDIM][4];
__device__ unsigned g_ticket;
__device__ unsigned g_count;
__device__ unsigned g_sense;

__device__ __forceinline__ unsigned packh2(float a, float b) {
    __half2 h = __floats2half2_rn(a, b);
    return *(unsigned*)&h;
}

__device__ __forceinline__ float fast_tanh(float x) {
    return 1.f - 2.f / (1.f + __expf(2.f * x));
}

__device__ __forceinline__ void mma16(float* c, const uint4& a, const uint2& b) {
    asm volatile(
        "mma.sync.aligned.m16n8k16.row.col.f32.f16.f16.f32 "
        "{%0,%1,%2,%3}, {%4,%5,%6,%7}, {%8,%9}, {%0,%1,%2,%3};\n"
        : "+f"(c[0]), "+f"(c[1]), "+f"(c[2]), "+f"(c[3])
        : "r"(a.x), "r"(a.y), "r"(a.z), "r"(a.w), "r"(b.x), "r"(b.y));
}

// word index (4B) of the half2 (col, col+1), col even, in a q/a2 fragment tile
__device__ __forceinline__ int q2addr(int row, int col) {
    const int mb = row >> 4, rho = row & 15;
    const int kb = col >> 4, kap = col & 15;
    return ((mb * KB16 + kb) * 32 + (rho & 7) * 4 + ((kap >> 1) & 3)) * 4 +
           (rho >> 3) + 2 * (kap >> 3);
}
// same for an h slab (8 kb blocks, 2 mb)
__device__ __forceinline__ int h2addr(int row, int col) {
    const int mb = row >> 4, rho = row & 15;
    const int kb = col >> 4, kap = col & 15;
    return ((mb * 8 + kb) * 32 + (rho & 7) * 4 + ((kap >> 1) & 3)) * 4 +
           (rho >> 3) + 2 * (kap >> 3);
}

__device__ __forceinline__ void gbar(int ncta, unsigned& sense) {
    __syncthreads();
    if (threadIdx.x == 0) {
        __threadfence();
        unsigned arrived = atomicAdd(&g_count, 1u) + 1u;
        if (arrived == (unsigned)ncta) {
            g_count = 0u;
            __threadfence();
            atomicAdd(&g_sense, 1u);
        } else {
            while ((int)(*(volatile unsigned*)&g_sense - (sense + 1u)) < 0) {
                __nanosleep(64);
            }
        }
    }
    sense += 1u;
    __syncthreads();
}

__global__ __launch_bounds__(256, 2) void spatial_gru_q32x2(
    const float* __restrict__ inputs, const float* __restrict__ Wr,
    const float* __restrict__ br, const float* __restrict__ Wz,
    const float* __restrict__ bz, const float* __restrict__ Wij,
    const float* __restrict__ bij, const float* __restrict__ WU,
    float* __restrict__ out, int ncta)
{
    extern __shared__ unsigned smem[];
    unsigned* qs = smem;
    unsigned* a2 = smem + QWH;
    const int tid = threadIdx.x;
    const int cta = blockIdx.x;
    const int gtid = cta * 256 + tid;
    const int gstride = ncta * 256;
    unsigned sense = *(volatile unsigned*)&g_sense;

    // ---------------- stage 0 -------------------------------------------
    if (gtid == 0) g_ticket = 0u;
    // pack weights -> fp16 fragments
    for (int idx = gtid; idx < 128 * KB16 * 32; idx += gstride) {
        const int lane = idx & 31;
        const int kb = (idx >> 5) % KB16;
        const int jblk = (idx >> 5) / KB16;
        const int jp = jblk * 8 + (lane >> 2);
        const int k = kb * 16 + (lane & 3) * 2;
        float w0, w1, w8, w9;
        if (jblk < 48) {
            const float* p = Wr + (size_t)jp * DD + k;
            w0 = p[0]; w1 = p[1]; w8 = p[8]; w9 = p[9];
        } else if (jblk < 112) {
            const int jz = jp - 384;
            const int j = (jz & 3) * 128 + (jz >> 2);
            const float* p = Wz + (size_t)j * DD + k;
            w0 = p[0]; w1 = p[1]; w8 = p[8]; w9 = p[9];
        } else {
            const int u = jp - 896;
            if (k < 384) {
                const float* p = WU + (size_t)u * 384 + k;
                w0 = p[0]; w1 = p[1]; w8 = p[8]; w9 = p[9];
            } else {
                const float* p = Wij + (size_t)u * 32 + (k - 384);
                w0 = p[0]; w1 = p[1]; w8 = p[8]; w9 = p[9];
            }
        }
        g_wph[jblk][kb][lane] = make_uint2(packh2(w0, w1), packh2(w8, w9));
    }
    // transpose inputs (B,C,L,R) -> fp16 (L,R,B,C)
    for (int idx = gtid; idx < BATCH * (CD / 2) * LDIM * (RDIM / 4); idx += gstride) {
        const int r4 = idx % (RDIM / 4);
        int t2 = idx / (RDIM / 4);
        const int l = t2 % LDIM; t2 /= LDIM;
        const int c2 = t2 & 15;
        const int b = t2 >> 4;
        const int c = c2 * 2, r0 = r4 * 4;
        const float* p0 = inputs + (((size_t)b * CD + c) * LDIM + l) * RDIM + r0;
        const float4 x0 = *(const float4*)p0;
        const float4 x1 = *(const float4*)(p0 + LDIM * RDIM);
        *(unsigned*)&g_sTh[l][r0 + 0][b][c] = packh2(x0.x, x1.x);
        *(unsigned*)&g_sTh[l][r0 + 1][b][c] = packh2(x0.y, x1.y);
        *(unsigned*)&g_sTh[l][r0 + 2][b][c] = packh2(x0.z, x1.z);
        *(unsigned*)&g_sTh[l][r0 + 3][b][c] = packh2(x0.w, x1.w);
    }
    for (int idx = gtid; idx < LDIM * RDIM * 4; idx += gstride)
        ((unsigned*)g_hflag)[idx] = 0u;
    gbar(ncta, sense);

    const int warp = tid >> 5, lane = tid & 31;
    const int l4 = lane >> 2;
    const int wn = warp;        // n-warp index; each warp covers both m-blocks

    // dynamic ticket walk state
    int dcur = 0;
    int dbase = 0;
    int nc = 1;   // nc(0) = 1

    int tkt = tid == 0 ? (int)atomicAdd(&g_ticket, 1u) : 0;
    __shared__ int s_tkt;
    for (;;) {
        if (tid == 0) s_tkt = tkt;
        __syncthreads();
        const int t = s_tkt;
        if (t >= NTASK) break;
        // advance diagonal pointer
        while (t >= dbase + 4 * nc) {
            dbase += 4 * nc;
            ++dcur;
            const int lo = (dcur > RDIM - 1) ? dcur - (RDIM - 1) : 0;
            const int hi = (dcur < LDIM - 1) ? dcur : LDIM - 1;
            nc = hi - lo + 1;
        }
        const int d = dcur;
        const int l0 = (d > RDIM - 1) ? d - (RDIM - 1) : 0;
        const int ti = t - dbase;
        const int ci = ti >> 2, qb = ti & 3;
        const int l = l0 + ci, rr = d - l;
        const int b0 = qb * 32;

        // -------- wait for neighbor h flags (tight poll) --------
        if (tid < 3) {
            volatile unsigned* f = 0;
            if (tid == 0)      { if (rr > 0) f = &g_hflag[l][rr - 1][qb]; }
            else if (tid == 1) { if (l > 0)  f = &g_hflag[l - 1][rr][qb]; }
            else               { if (l > 0 && rr > 0) f = &g_hflag[l - 1][rr - 1][qb]; }
            if (f) {
                while (*f == 0u) { }
                __threadfence();
            }
        }
        __syncthreads();

        const uint4* ghtop  = (l > 0)  ? (const uint4*)&g_hhalf[l - 1][rr][qb][0] : (const uint4*)0;
        const uint4* ghleft = (rr > 0) ? (const uint4*)&g_hhalf[l][rr - 1][qb][0] : (const uint4*)0;
        const uint4* ghdiag = (l > 0 && rr > 0)
                             ? (const uint4*)&g_hhalf[l - 1][rr - 1][qb][0] : (const uint4*)0;

        // -------- build q: h regions are direct fragment copies --------
        for (int idx = tid; idx < 1536; idx += 256) {
            const int ln = idx & 31;
            const int kq = (idx >> 5) % 24;
            const int mb = (idx >> 5) / 24;
            const uint4* src;
            if (kq < 8)       src = ghtop;
            else if (kq < 16) src = ghleft;
            else              src = ghdiag;
            uint4 v = make_uint4(0u, 0u, 0u, 0u);
            if (src) v = src[(mb * 8 + (kq & 7)) * 32 + ln];
            *(uint4*)(qs + ((mb * KB16 + kq) * 32 + ln) * 4) = v;
        }
        // s region (q kb 24,25)
        if (tid < 128) {
            const int ln = tid & 31;
            const int kb2 = (tid >> 5) & 1;
            const int mb = tid >> 6;
            const int row = b0 + mb * 16 + (ln >> 2);
            const int c0 = kb2 * 16 + (ln & 3) * 2;
            const __half* s0 = &g_sTh[l][rr][row][0];
            const __half* s1 = &g_sTh[l][rr][row + 8][0];
            uint4 v;
            v.x = *(const unsigned*)(s0 + c0);
            v.y = *(const unsigned*)(s1 + c0);
            v.z = *(const unsigned*)(s0 + c0 + 8);
            v.w = *(const unsigned*)(s1 + c0 + 8);
            *(uint4*)(qs + ((mb * KB16 + 24 + kb2) * 32 + ln) * 4) = v;
        }
        __syncthreads();

        // ================= GEMM1-r: N=384, warp = 2mt x 6 jblk =========
        {
            const int jb = wn * 6;
            float acc[2][6][4];
#pragma unroll
            for (int mt = 0; mt < 2; ++mt)
#pragma unroll
                for (int nt = 0; nt < 6; ++nt)
#pragma unroll
                    for (int i = 0; i < 4; ++i) acc[mt][nt][i] = 0.f;
            uint2 wb[2][6];
#pragma unroll
            for (int nt = 0; nt < 6; ++nt) {
                wb[0][nt] = g_wph[jb + nt][0][lane];
                wb[1][nt] = g_wph[jb + nt][1][lane];
            }
#pragma unroll 2
            for (int kb = 0; kb < KB16; ++kb) {
                const int par = kb & 1;
                uint4 av[2];
#pragma unroll
                for (int mt = 0; mt < 2; ++mt)
                    av[mt] = *(const uint4*)(qs + ((mt * KB16 + kb) * 32 + lane) * 4);
#pragma unroll
                for (int mt = 0; mt < 2; ++mt)
#pragma unroll
                    for (int nt = 0; nt < 6; ++nt)
                        mma16(acc[mt][nt], av[mt], wb[par][nt]);
#pragma unroll
                for (int nt = 0; nt < 6; ++nt)
                    wb[par][nt] = g_wph[jb + nt][kb + 2][lane];
            }
            // a2 = sigmoid(r + br) * h (block-swapped source)
#pragma unroll
            for (int nt = 0; nt < 6; ++nt) {
                const int col0 = (jb + nt) * 8 + (lane & 3) * 2;
                const float b0r = br[col0], b1r = br[col0 + 1];
                const int qc0 = (col0 < 128) ? col0 + 128
                              : (col0 < 256) ? col0 - 128 : col0;
#pragma unroll
                for (int mt = 0; mt < 2; ++mt) {
#pragma unroll
                    for (int rs = 0; rs < 2; ++rs) {
                        const int rowl = mt * 16 + l4 + rs * 8;
                        const unsigned hv = qs[q2addr(rowl, qc0)];
                        const __half2 hh = *(const __half2*)&hv;
                        const float p0 = acc[mt][nt][rs * 2 + 0] + b0r;
                        const float p1 = acc[mt][nt][rs * 2 + 1] + b1r;
                        const float v0 = __low2float(hh) / (1.f + __expf(-p0));
                        const float v1 = __high2float(hh) / (1.f + __expf(-p1));
                        a2[q2addr(rowl, col0)] = packh2(v0, v1);
                    }
                }
            }
        }
        // copy s blocks q -> a2
        if (tid < 128) {
            const int ln = tid & 31;
            const int kb2 = (tid >> 5) & 1;
            const int mb = tid >> 6;
            const int off = (mb * KB16 + 24 + kb2) * 32 + ln;
            ((uint4*)a2)[off] = ((const uint4*)qs)[off];
        }

        // ================= GEMM1-z: N=512 interleaved, 2mt x 8 jblk ====
        float accz[2][8][4];
        {
            const int jb = 48 + wn * 8;
#pragma unroll
            for (int mt = 0; mt < 2; ++mt)
#pragma unroll
                for (int nt = 0; nt < 8; ++nt)
#pragma unroll
                    for (int i = 0; i < 4; ++i) accz[mt][nt][i] = 0.f;
            uint2 wb[2][8];
#pragma unroll
            for (int nt = 0; nt < 8; ++nt) {
                wb[0][nt] = g_wph[jb + nt][0][lane];
                wb[1][nt] = g_wph[jb + nt][1][lane];
            }
#pragma unroll 2
            for (int kb = 0; kb < KB16; ++kb) {
                const int par = kb & 1;
                uint4 av[2];
#pragma unroll
                for (int mt = 0; mt < 2; ++mt)
                    av[mt] = *(const uint4*)(qs + ((mt * KB16 + kb) * 32 + lane) * 4);
#pragma unroll
                for (int mt = 0; mt < 2; ++mt)
#pragma unroll
                    for (int nt = 0; nt < 8; ++nt)
                        mma16(accz[mt][nt], av[mt], wb[par][nt]);
#pragma unroll
                for (int nt = 0; nt < 8; ++nt)
                    wb[par][nt] = g_wph[jb + nt][kb + 2][lane];
            }
            // register softmax over 4 z-groups (partner lane^1) + hmix
            const __half* qh = (const __half*)qs;
#pragma unroll
            for (int nt = 0; nt < 8; ++nt) {
                const int pcol = (jb + nt) * 8 - 384 + (lane & 3) * 2;
                const int u = pcol >> 2;
                const int gb = pcol & 3;
                const bool ev = (gb == 0);
                const float bz0 = bz[gb * 128 + u];
                const float bz1 = bz[(gb + 1) * 128 + u];
#pragma unroll
                for (int mt = 0; mt < 2; ++mt) {
#pragma unroll
                    for (int rs = 0; rs < 2; ++rs) {
                        const int row = mt * 16 + l4 + rs * 8;
                        const float v0 = accz[mt][nt][rs * 2 + 0] + bz0;
                        const float v1 = accz[mt][nt][rs * 2 + 1] + bz1;
                        float m = fmaxf(v0, v1);
                        m = fmaxf(m, __shfl_xor_sync(0xffffffffu, m, 1));
                        const float e0 = __expf(v0 - m), e1 = __expf(v1 - m);
                        float s = e0 + e1;
                        s += __shfl_xor_sync(0xffffffffu, s, 1);
                        const float inv = 1.f / s;
                        float part;
                        if (ev) {
                            const int c = 128 + u;
                            const float hlv = __half2float(
                                qh[q2addr(row, c & ~1) * 2 + (c & 1)]);
                            part = e1 * hlv;
                        } else {
                            const float htv = __half2float(
                                qh[q2addr(row, u & ~1) * 2 + (u & 1)]);
                            const int c = 256 + u;
                            const float hdv = __half2float(
                                qh[q2addr(row, c & ~1) * 2 + (c & 1)]);
                            part = e0 * htv + e1 * hdv;
                        }
                        const float hm = (part + __shfl_xor_sync(0xffffffffu, part, 1)) * inv;
                        accz[mt][nt][rs * 2 + 0] = e0 * inv;   // zi (even lanes)
                        accz[mt][nt][rs * 2 + 1] = hm;
                    }
                }
            }
        }
        __syncthreads();   // all q reads + a2 writes done

        // stash (zi, hmix) as half2 into dead q region, padded stride 132
        unsigned* hmz = smem;
        if ((lane & 1) == 0) {
            const int jb = 48 + wn * 8;
#pragma unroll
            for (int nt = 0; nt < 8; ++nt) {
                const int pcol = (jb + nt) * 8 - 384 + (lane & 3) * 2;
                const int u = pcol >> 2;
#pragma unroll
                for (int mt = 0; mt < 2; ++mt) {
#pragma unroll
                    for (int rs = 0; rs < 2; ++rs) {
                        const int row = mt * 16 + l4 + rs * 8;
                        hmz[row * 132 + u] = packh2(accz[mt][nt][rs * 2 + 0],
                                                    accz[mt][nt][rs * 2 + 1]);
                    }
                }
            }
        }
        __syncthreads();

        // ================= GEMM2: N=128, warp = 2mt x 2 jblk ===========
        {
            const int jb = 112 + wn * 2;
            float acc2[2][2][4];
#pragma unroll
            for (int mt = 0; mt < 2; ++mt)
#pragma unroll
                for (int nt = 0; nt < 2; ++nt)
#pragma unroll
                    for (int i = 0; i < 4; ++i) acc2[mt][nt][i] = 0.f;
            uint2 wb[2][2];
#pragma unroll
            for (int nt = 0; nt < 2; ++nt) {
                wb[0][nt] = g_wph[jb + nt][0][lane];
                wb[1][nt] = g_wph[jb + nt][1][lane];
            }
#pragma unroll 2
            for (int kb = 0; kb < KB16; ++kb) {
                const int par = kb & 1;
                uint4 av[2];
#pragma unroll
                for (int mt = 0; mt < 2; ++mt)
                    av[mt] = *(const uint4*)(a2 + ((mt * KB16 + kb) * 32 + lane) * 4);
#pragma unroll
                for (int mt = 0; mt < 2; ++mt)
#pragma unroll
                    for (int nt = 0; nt < 2; ++nt)
                        mma16(acc2[mt][nt], av[mt], wb[par][nt]);
#pragma unroll
                for (int nt = 0; nt < 2; ++nt)
                    wb[par][nt] = g_wph[jb + nt][kb + 2][lane];
            }
            // h = hmix + zi * tanh(ghat + bij); write fragment h slab
            unsigned* ghout = &g_hhalf[l][rr][qb][0];
#pragma unroll
            for (int nt = 0; nt < 2; ++nt) {
                const int u0 = (wn * 2 + nt) * 8 + (lane & 3) * 2;
                const float2 bj = *(const float2*)(bij + u0);
#pragma unroll
                for (int mt = 0; mt < 2; ++mt) {
#pragma unroll
                    for (int rs = 0; rs < 2; ++rs) {
                        const int rowl = mt * 16 + l4 + rs * 8;
                        const unsigned m0 = hmz[rowl * 132 + u0];
                        const unsigned m1 = hmz[rowl * 132 + u0 + 1];
                        const __half2 z0 = *(const __half2*)&m0;
                        const __half2 z1 = *(const __half2*)&m1;
                        const float h0 = __high2float(z0) + __low2float(z0) *
                            fast_tanh(acc2[mt][nt][rs * 2 + 0] + bj.x);
                        const float h1 = __high2float(z1) + __low2float(z1) *
                            fast_tanh(acc2[mt][nt][rs * 2 + 1] + bj.y);
                        __stcg(ghout + h2addr(rowl, u0), packh2(h0, h1));
                        if (d == NDIAG - 1)
                            *(float2*)(out + (size_t)(b0 + rowl) * UD + u0) =
                                make_float2(h0, h1);
                    }
                }
            }
        }
        __threadfence();
        __syncthreads();
        if (tid == 0) {
            *(volatile unsigned*)&g_hflag[l][rr][qb] = 1u;
            tkt = (int)atomicAdd(&g_ticket, 1u);
        }
    }
}

// ---------------------------------------------------------------------------
extern "C" void kernel_launch(void* const* d_in, const int* in_sizes, int n_in,
                              void* d_out, int out_size)
{
    const float* inputs = (const float*)d_in[0];
    const float* Wr     = (const float*)d_in[1];
    const float* br     = (const float*)d_in[2];
    const float* Wz     = (const float*)d_in[3];
    const float* bz     = (const float*)d_in[4];
    const float* Wij    = (const float*)d_in[5];
    const float* bij    = (const float*)d_in[6];
    const float* WU     = (const float*)d_in[7];
    float* out = (float*)d_out;

    const int SMEM = 2 * QWH * (int)sizeof(unsigned);   // 53248 B per CTA
    cudaFuncSetAttribute(spatial_gru_q32x2,
                         cudaFuncAttributeMaxDynamicSharedMemorySize, SMEM);
    int dev = 0;
    cudaGetDevice(&dev);
    int nsm = 0;
    cudaDeviceGetAttribute(&nsm, cudaDevAttrMultiProcessorCount, dev);
    const int ncta = nsm * 2;   // 2 CTAs/SM; grid == resident CTAs (deadlock-free)

    spatial_gru_q32x2<<<ncta, 256, SMEM>>>(inputs, Wr, br, Wz, bz, Wij, bij,
                                           WU, out, ncta);
}

// round 14
// speedup vs baseline: 1.1233x; 1.1233x over previous
#include <cuda_runtime.h>
#include <cuda_fp16.h>

#define LDIM 80
#define RDIM 80
#define BATCH 128
#define UD 128
#define CD 32
#define DD 416
#define NDIAG 159
#define KB16 26          // 416 / 16
#define KBW 28           // padded for prefetch
#define QWH (2 * KB16 * 32 * 4)   // uint words per 32x416 fp16 fragment tile
#define NTASK 25600               // sum over d of 4*nc

// Fragment-packed fp16 h per (l, r, qb): [2 mb][8 kb][32 lanes] uint4 = 8 KB slab.
__device__ unsigned g_hhalf[LDIM][RDIM][4][2 * 8 * 32 * 4];   // ~105 MB
// fp16 inputs, (l, r, b, c) layout.
__device__ __half   g_sTh[LDIM][RDIM][BATCH][CD];             // ~52 MB
// Fragment-packed fp16 weights: jblk 0..47 Wr; 48..111 Wz interleaved; 112..127 [WU|Wij]
__device__ uint2    g_wph[128][KBW][32];
// Dataflow flags + ticket.
__device__ unsigned g_hflag[LDIM][RDIM][4];
__device__ unsigned g_ticket;
__device__ unsigned g_count;
__device__ unsigned g_sense;

__device__ __forceinline__ unsigned packh2(float a, float b) {
    __half2 h = __floats2half2_rn(a, b);
    return *(unsigned*)&h;
}

__device__ __forceinline__ float fast_tanh(float x) {
    return 1.f - 2.f / (1.f + __expf(2.f * x));
}

__device__ __forceinline__ void mma16(float* c, const uint4& a, const uint2& b) {
    asm volatile(
        "mma.sync.aligned.m16n8k16.row.col.f32.f16.f16.f32 "
        "{%0,%1,%2,%3}, {%4,%5,%6,%7}, {%8,%9}, {%0,%1,%2,%3};\n"
        : "+f"(c[0]), "+f"(c[1]), "+f"(c[2]), "+f"(c[3])
        : "r"(a.x), "r"(a.y), "r"(a.z), "r"(a.w), "r"(b.x), "r"(b.y));
}

__device__ __forceinline__ unsigned ld_acq(const unsigned* p) {
    unsigned v;
    asm volatile("ld.acquire.gpu.global.u32 %0, [%1];" : "=r"(v) : "l"(p) : "memory");
    return v;
}
__device__ __forceinline__ void st_rel(unsigned* p, unsigned v) {
    asm volatile("st.release.gpu.global.u32 [%0], %1;" :: "l"(p), "r"(v) : "memory");
}

// word index (4B) of the half2 (col, col+1), col even, in a q/a2 fragment tile
__device__ __forceinline__ int q2addr(int row, int col) {
    const int mb = row >> 4, rho = row & 15;
    const int kb = col >> 4, kap = col & 15;
    return ((mb * KB16 + kb) * 32 + (rho & 7) * 4 + ((kap >> 1) & 3)) * 4 +
           (rho >> 3) + 2 * (kap >> 3);
}
// same for an h slab (8 kb blocks, 2 mb)
__device__ __forceinline__ int h2addr(int row, int col) {
    const int mb = row >> 4, rho = row & 15;
    const int kb = col >> 4, kap = col & 15;
    return ((mb * 8 + kb) * 32 + (rho & 7) * 4 + ((kap >> 1) & 3)) * 4 +
           (rho >> 3) + 2 * (kap >> 3);
}

__device__ __forceinline__ void gbar(int ncta, unsigned& sense) {
    __syncthreads();
    if (threadIdx.x == 0) {
        __threadfence();
        unsigned arrived = atomicAdd(&g_count, 1u) + 1u;
        if (arrived == (unsigned)ncta) {
            g_count = 0u;
            __threadfence();
            atomicAdd(&g_sense, 1u);
        } else {
            while ((int)(*(volatile unsigned*)&g_sense - (sense + 1u)) < 0) {
                __nanosleep(64);
            }
        }
    }
    sense += 1u;
    __syncthreads();
}

__global__ __launch_bounds__(512, 1) void spatial_gru_m1(
    const float* __restrict__ inputs, const float* __restrict__ Wr,
    const float* __restrict__ br, const float* __restrict__ Wz,
    const float* __restrict__ bz, const float* __restrict__ Wij,
    const float* __restrict__ bij, const float* __restrict__ WU,
    float* __restrict__ out, int ncta)
{
    extern __shared__ unsigned smem[];
    unsigned* qs = smem;
    unsigned* a2 = smem + QWH;
    const int tid = threadIdx.x;
    const int cta = blockIdx.x;
    const int gtid = cta * 512 + tid;
    const int gstride = ncta * 512;
    unsigned sense = *(volatile unsigned*)&g_sense;

    // ---------------- stage 0 -------------------------------------------
    if (gtid == 0) g_ticket = 0u;
    // pack weights -> fp16 fragments
    for (int idx = gtid; idx < 128 * KB16 * 32; idx += gstride) {
        const int lane = idx & 31;
        const int kb = (idx >> 5) % KB16;
        const int jblk = (idx >> 5) / KB16;
        const int jp = jblk * 8 + (lane >> 2);
        const int k = kb * 16 + (lane & 3) * 2;
        float w0, w1, w8, w9;
        if (jblk < 48) {
            const float* p = Wr + (size_t)jp * DD + k;
            w0 = p[0]; w1 = p[1]; w8 = p[8]; w9 = p[9];
        } else if (jblk < 112) {
            const int jz = jp - 384;
            const int j = (jz & 3) * 128 + (jz >> 2);
            const float* p = Wz + (size_t)j * DD + k;
            w0 = p[0]; w1 = p[1]; w8 = p[8]; w9 = p[9];
        } else {
            const int u = jp - 896;
            if (k < 384) {
                const float* p = WU + (size_t)u * 384 + k;
                w0 = p[0]; w1 = p[1]; w8 = p[8]; w9 = p[9];
            } else {
                const float* p = Wij + (size_t)u * 32 + (k - 384);
                w0 = p[0]; w1 = p[1]; w8 = p[8]; w9 = p[9];
            }
        }
        g_wph[jblk][kb][lane] = make_uint2(packh2(w0, w1), packh2(w8, w9));
    }
    // transpose inputs (B,C,L,R) -> fp16 (L,R,B,C)
    for (int idx = gtid; idx < BATCH * (CD / 2) * LDIM * (RDIM / 4); idx += gstride) {
        const int r4 = idx % (RDIM / 4);
        int t2 = idx / (RDIM / 4);
        const int l = t2 % LDIM; t2 /= LDIM;
        const int c2 = t2 & 15;
        const int b = t2 >> 4;
        const int c = c2 * 2, r0 = r4 * 4;
        const float* p0 = inputs + (((size_t)b * CD + c) * LDIM + l) * RDIM + r0;
        const float4 x0 = *(const float4*)p0;
        const float4 x1 = *(const float4*)(p0 + LDIM * RDIM);
        *(unsigned*)&g_sTh[l][r0 + 0][b][c] = packh2(x0.x, x1.x);
        *(unsigned*)&g_sTh[l][r0 + 1][b][c] = packh2(x0.y, x1.y);
        *(unsigned*)&g_sTh[l][r0 + 2][b][c] = packh2(x0.z, x1.z);
        *(unsigned*)&g_sTh[l][r0 + 3][b][c] = packh2(x0.w, x1.w);
    }
    for (int idx = gtid; idx < LDIM * RDIM * 4; idx += gstride)
        ((unsigned*)g_hflag)[idx] = 0u;
    gbar(ncta, sense);

    const int w = tid >> 5, lane = tid & 31;
    const int l4 = lane >> 2;

    // dynamic ticket walk state
    int dcur = 0;
    int dbase = 0;
    int nc = 1;   // nc(0) = 1

    int tkt = tid == 0 ? (int)atomicAdd(&g_ticket, 1u) : 0;
    __shared__ int s_tkt;
    for (;;) {
        if (tid == 0) s_tkt = tkt;
        __syncthreads();
        const int t = s_tkt;
        if (t >= NTASK) break;
        // prefetch NEXT ticket now (hides the L2 atomic behind the task body)
        if (tid == 0) tkt = (int)atomicAdd(&g_ticket, 1u);
        // advance diagonal pointer
        while (t >= dbase + 4 * nc) {
            dbase += 4 * nc;
            ++dcur;
            const int lo = (dcur > RDIM - 1) ? dcur - (RDIM - 1) : 0;
            const int hi = (dcur < LDIM - 1) ? dcur : LDIM - 1;
            nc = hi - lo + 1;
        }
        const int d = dcur;
        const int l0 = (d > RDIM - 1) ? d - (RDIM - 1) : 0;
        const int ti = t - dbase;
        const int ci = ti >> 2, qb = ti & 3;
        const int l = l0 + ci, rr = d - l;
        const int b0 = qb * 32;

        // -------- wait for neighbor h flags (acquire poll) --------
        if (tid < 3) {
            const unsigned* f = 0;
            if (tid == 0)      { if (rr > 0) f = &g_hflag[l][rr - 1][qb]; }
            else if (tid == 1) { if (l > 0)  f = &g_hflag[l - 1][rr][qb]; }
            else               { if (l > 0 && rr > 0) f = &g_hflag[l - 1][rr - 1][qb]; }
            if (f) {
                while (ld_acq(f) == 0u) { }
            }
        }
        __syncthreads();

        const uint4* ghtop  = (l > 0)  ? (const uint4*)&g_hhalf[l - 1][rr][qb][0] : (const uint4*)0;
        const uint4* ghleft = (rr > 0) ? (const uint4*)&g_hhalf[l][rr - 1][qb][0] : (const uint4*)0;
        const uint4* ghdiag = (l > 0 && rr > 0)
                             ? (const uint4*)&g_hhalf[l - 1][rr - 1][qb][0] : (const uint4*)0;

        // -------- build q: h regions are direct fragment copies --------
        for (int idx = tid; idx < 1536; idx += 512) {
            const int ln = idx & 31;
            const int kq = (idx >> 5) % 24;
            const int mb = (idx >> 5) / 24;
            const uint4* src;
            if (kq < 8)       src = ghtop;
            else if (kq < 16) src = ghleft;
            else              src = ghdiag;
            uint4 v = make_uint4(0u, 0u, 0u, 0u);
            if (src) v = src[(mb * 8 + (kq & 7)) * 32 + ln];
            *(uint4*)(qs + ((mb * KB16 + kq) * 32 + ln) * 4) = v;
        }
        // s region (q kb 24,25)
        if (tid < 128) {
            const int ln = tid & 31;
            const int kb2 = (tid >> 5) & 1;
            const int mb = tid >> 6;
            const int row = b0 + mb * 16 + (ln >> 2);
            const int c0 = kb2 * 16 + (ln & 3) * 2;
            const __half* s0 = &g_sTh[l][rr][row][0];
            const __half* s1 = &g_sTh[l][rr][row + 8][0];
            uint4 v;
            v.x = *(const unsigned*)(s0 + c0);
            v.y = *(const unsigned*)(s1 + c0);
            v.z = *(const unsigned*)(s0 + c0 + 8);
            v.w = *(const unsigned*)(s1 + c0 + 8);
            *(uint4*)(qs + ((mb * KB16 + 24 + kb2) * 32 + ln) * 4) = v;
        }
        __syncthreads();

        // ======= merged GEMM1 (r: 3 jblks, z: 4 jblks) x 2 m-blocks =======
        float accr[2][3][4];
        float accz[2][4][4];
        {
#pragma unroll
            for (int mt = 0; mt < 2; ++mt) {
#pragma unroll
                for (int nt = 0; nt < 3; ++nt)
#pragma unroll
                    for (int i = 0; i < 4; ++i) accr[mt][nt][i] = 0.f;
#pragma unroll
                for (int nt = 0; nt < 4; ++nt)
#pragma unroll
                    for (int i = 0; i < 4; ++i) accz[mt][nt][i] = 0.f;
            }
            uint2 wb[2][7];
#pragma unroll
            for (int j = 0; j < 7; ++j) {
                const int jblk = (j < 3) ? (j * 16 + w) : (48 + (j - 3) * 16 + w);
                wb[0][j] = g_wph[jblk][0][lane];
                wb[1][j] = g_wph[jblk][1][lane];
            }
#pragma unroll 2
            for (int kb = 0; kb < KB16; ++kb) {
                const int par = kb & 1;
                uint4 av[2];
#pragma unroll
                for (int mt = 0; mt < 2; ++mt)
                    av[mt] = *(const uint4*)(qs + ((mt * KB16 + kb) * 32 + lane) * 4);
#pragma unroll
                for (int mt = 0; mt < 2; ++mt) {
#pragma unroll
                    for (int nt = 0; nt < 3; ++nt)
                        mma16(accr[mt][nt], av[mt], wb[par][nt]);
#pragma unroll
                    for (int nt = 0; nt < 4; ++nt)
                        mma16(accz[mt][nt], av[mt], wb[par][3 + nt]);
                }
#pragma unroll
                for (int j = 0; j < 7; ++j) {
                    const int jblk = (j < 3) ? (j * 16 + w) : (48 + (j - 3) * 16 + w);
                    wb[par][j] = g_wph[jblk][kb + 2][lane];
                }
            }
        }

        // -------- r-epilogue: a2 = sigmoid(r + br) * h --------
#pragma unroll
        for (int nt = 0; nt < 3; ++nt) {
            const int jblk = nt * 16 + w;
            const int col0 = jblk * 8 + (lane & 3) * 2;
            const float b0r = br[col0], b1r = br[col0 + 1];
            const int qc0 = (col0 < 128) ? col0 + 128
                          : (col0 < 256) ? col0 - 128 : col0;
#pragma unroll
            for (int mt = 0; mt < 2; ++mt) {
#pragma unroll
                for (int rs = 0; rs < 2; ++rs) {
                    const int rowl = mt * 16 + l4 + rs * 8;
                    const unsigned hv = qs[q2addr(rowl, qc0)];
                    const __half2 hh = *(const __half2*)&hv;
                    const float p0 = accr[mt][nt][rs * 2 + 0] + b0r;
                    const float p1 = accr[mt][nt][rs * 2 + 1] + b1r;
                    const float v0 = __low2float(hh) / (1.f + __expf(-p0));
                    const float v1 = __high2float(hh) / (1.f + __expf(-p1));
                    a2[q2addr(rowl, col0)] = packh2(v0, v1);
                }
            }
        }
        // copy s blocks q -> a2 (reads q kb 24/25, before hmz stash)
        if (tid < 128) {
            const int ln = tid & 31;
            const int kb2 = (tid >> 5) & 1;
            const int mb = tid >> 6;
            const int off = (mb * KB16 + 24 + kb2) * 32 + ln;
            ((uint4*)a2)[off] = ((const uint4*)qs)[off];
        }

        // -------- z-epilogue: register softmax (partner lane^1) + hmix ----
        {
            const __half* qh = (const __half*)qs;
#pragma unroll
            for (int nt = 0; nt < 4; ++nt) {
                const int jblk = 48 + nt * 16 + w;
                const int pcol = (jblk - 48) * 8 + (lane & 3) * 2;
                const int u = pcol >> 2;
                const int gb = pcol & 3;
                const bool ev = (gb == 0);
                const float bz0 = bz[gb * 128 + u];
                const float bz1 = bz[(gb + 1) * 128 + u];
#pragma unroll
                for (int mt = 0; mt < 2; ++mt) {
#pragma unroll
                    for (int rs = 0; rs < 2; ++rs) {
                        const int row = mt * 16 + l4 + rs * 8;
                        const float v0 = accz[mt][nt][rs * 2 + 0] + bz0;
                        const float v1 = accz[mt][nt][rs * 2 + 1] + bz1;
                        float m = fmaxf(v0, v1);
                        m = fmaxf(m, __shfl_xor_sync(0xffffffffu, m, 1));
                        const float e0 = __expf(v0 - m), e1 = __expf(v1 - m);
                        float s = e0 + e1;
                        s += __shfl_xor_sync(0xffffffffu, s, 1);
                        const float inv = 1.f / s;
                        float part;
                        if (ev) {
                            const int c = 128 + u;
                            const float hlv = __half2float(
                                qh[q2addr(row, c & ~1) * 2 + (c & 1)]);
                            part = e1 * hlv;
                        } else {
                            const float htv = __half2float(
                                qh[q2addr(row, u & ~1) * 2 + (u & 1)]);
                            const int c = 256 + u;
                            const float hdv = __half2float(
                                qh[q2addr(row, c & ~1) * 2 + (c & 1)]);
                            part = e0 * htv + e1 * hdv;
                        }
                        const float hm = (part + __shfl_xor_sync(0xffffffffu, part, 1)) * inv;
                        accz[mt][nt][rs * 2 + 0] = e0 * inv;   // zi (even lanes)
                        accz[mt][nt][rs * 2 + 1] = hm;
                    }
                }
            }
        }
        __syncthreads();   // all q reads + a2 writes done

        // stash (zi, hmix) as half2 into dead q region, padded stride 132
        unsigned* hmz = smem;
        if ((lane & 1) == 0) {
#pragma unroll
            for (int nt = 0; nt < 4; ++nt) {
                const int jblk = 48 + nt * 16 + w;
                const int pcol = (jblk - 48) * 8 + (lane & 3) * 2;
                const int u = pcol >> 2;
#pragma unroll
                for (int mt = 0; mt < 2; ++mt) {
#pragma unroll
                    for (int rs = 0; rs < 2; ++rs) {
                        const int row = mt * 16 + l4 + rs * 8;
                        hmz[row * 132 + u] = packh2(accz[mt][nt][rs * 2 + 0],
                                                    accz[mt][nt][rs * 2 + 1]);
                    }
                }
            }
        }
        __syncthreads();

        // ================= GEMM2: 1 jblk x 2 m-blocks per warp ===========
        {
            const int jb = 112 + w;
            float acc2[2][4];
#pragma unroll
            for (int mt = 0; mt < 2; ++mt)
#pragma unroll
                for (int i = 0; i < 4; ++i) acc2[mt][i] = 0.f;
            uint2 wb2[2];
            wb2[0] = g_wph[jb][0][lane];
            wb2[1] = g_wph[jb][1][lane];
#pragma unroll 2
            for (int kb = 0; kb < KB16; ++kb) {
                const int par = kb & 1;
                uint4 av[2];
#pragma unroll
                for (int mt = 0; mt < 2; ++mt)
                    av[mt] = *(const uint4*)(a2 + ((mt * KB16 + kb) * 32 + lane) * 4);
#pragma unroll
                for (int mt = 0; mt < 2; ++mt)
                    mma16(acc2[mt], av[mt], wb2[par]);
                wb2[par] = g_wph[jb][kb + 2][lane];
            }
            // h = hmix + zi * tanh(ghat + bij); write fragment h slab
            unsigned* ghout = &g_hhalf[l][rr][qb][0];
            const int u0 = w * 8 + (lane & 3) * 2;
            const float2 bj = *(const float2*)(bij + u0);
#pragma unroll
            for (int mt = 0; mt < 2; ++mt) {
#pragma unroll
                for (int rs = 0; rs < 2; ++rs) {
                    const int rowl = mt * 16 + l4 + rs * 8;
                    const unsigned m0 = hmz[rowl * 132 + u0];
                    const unsigned m1 = hmz[rowl * 132 + u0 + 1];
                    const __half2 z0 = *(const __half2*)&m0;
                    const __half2 z1 = *(const __half2*)&m1;
                    const float h0 = __high2float(z0) + __low2float(z0) *
                        fast_tanh(acc2[mt][rs * 2 + 0] + bj.x);
                    const float h1 = __high2float(z1) + __low2float(z1) *
                        fast_tanh(acc2[mt][rs * 2 + 1] + bj.y);
                    __stcg(ghout + h2addr(rowl, u0), packh2(h0, h1));
                    if (d == NDIAG - 1)
                        *(float2*)(out + (size_t)(b0 + rowl) * UD + u0) =
                            make_float2(h0, h1);
                }
            }
        }
        __syncthreads();
        if (tid == 0) st_rel(&g_hflag[l][rr][qb], 1u);
    }
}

// ---------------------------------------------------------------------------
extern "C" void kernel_launch(void* const* d_in, const int* in_sizes, int n_in,
                              void* d_out, int out_size)
{
    const float* inputs = (const float*)d_in[0];
    const float* Wr     = (const float*)d_in[1];
    const float* br     = (const float*)d_in[2];
    const float* Wz     = (const float*)d_in[3];
    const float* bz     = (const float*)d_in[4];
    const float* Wij    = (const float*)d_in[5];
    const float* bij    = (const float*)d_in[6];
    const float* WU     = (const float*)d_in[7];
    float* out = (float*)d_out;

    const int SMEM = 2 * QWH * (int)sizeof(unsigned);   // 53248 B
    cudaFuncSetAttribute(spatial_gru_m1,
                         cudaFuncAttributeMaxDynamicSharedMemorySize, SMEM);
    int dev = 0;
    cudaGetDevice(&dev);
    int nsm = 0;
    cudaDeviceGetAttribute(&nsm, cudaDevAttrMultiProcessorCount, dev);
    const int ncta = nsm;   // 1 CTA/SM; grid == resident CTAs (deadlock-free)

    spatial_gru_m1<<<ncta, 512, SMEM>>>(inputs, Wr, br, Wz, bz, Wij, bij,
                                        WU, out, ncta);
}

// round 17
// speedup vs baseline: 1.3178x; 1.1731x over previous
#include <cuda_runtime.h>
#include <cuda_fp16.h>

#define LDIM 80
#define RDIM 80
#define BATCH 128
#define UD 128
#define CD 32
#define DD 416
#define NDIAG 159
#define KB16 26          // 416 / 16
#define KBW 28           // padded for prefetch
#define QWH (2 * KB16 * 32 * 4)   // uint words per 32x416 fp16 fragment tile
#define HMZ0 (2 * QWH)            // hmz region start (words)
#define NTASK 25600               // sum over d of 4*nc

// Fragment-packed fp16 h per (l, r, qb): [2 mb][8 kb][32 lanes] uint4 = 8 KB slab.
__device__ unsigned g_hhalf[LDIM][RDIM][4][2 * 8 * 32 * 4];   // ~105 MB
// fp16 inputs, (l, r, b, c) layout.
__device__ __half   g_sTh[LDIM][RDIM][BATCH][CD];             // ~52 MB
// Fragment-packed fp16 weights: jblk 0..47 Wr; 48..111 Wz interleaved; 112..127 [WU|Wij]
__device__ uint2    g_wph[128][KBW][32];
// Dataflow flags + ticket.
__device__ unsigned g_hflag[LDIM][RDIM][4];
__device__ unsigned g_ticket;
__device__ unsigned g_count;
__device__ unsigned g_sense;

__device__ __forceinline__ unsigned packh2(float a, float b) {
    __half2 h = __floats2half2_rn(a, b);
    return *(unsigned*)&h;
}

__device__ __forceinline__ float fast_sig(float x) {
    // 1 / (1 + e^-x) via fast division
    return __fdividef(1.f, 1.f + __expf(-x));
}
__device__ __forceinline__ float fast_tanh(float x) {
    return 1.f - __fdividef(2.f, 1.f + __expf(2.f * x));
}

__device__ __forceinline__ void mma16(float* c, const uint4& a, const uint2& b) {
    asm volatile(
        "mma.sync.aligned.m16n8k16.row.col.f32.f16.f16.f32 "
        "{%0,%1,%2,%3}, {%4,%5,%6,%7}, {%8,%9}, {%0,%1,%2,%3};\n"
        : "+f"(c[0]), "+f"(c[1]), "+f"(c[2]), "+f"(c[3])
        : "r"(a.x), "r"(a.y), "r"(a.z), "r"(a.w), "r"(b.x), "r"(b.y));
}

__device__ __forceinline__ unsigned ld_acq(const unsigned* p) {
    unsigned v;
    asm volatile("ld.acquire.gpu.global.u32 %0, [%1];" : "=r"(v) : "l"(p) : "memory");
    return v;
}
__device__ __forceinline__ void st_rel(unsigned* p, unsigned v) {
    asm volatile("st.release.gpu.global.u32 [%0], %1;" :: "l"(p), "r"(v) : "memory");
}

// word index (4B) of the half2 (col, col+1), col even, in a q/a2 fragment tile
__device__ __forceinline__ int q2addr(int row, int col) {
    const int mb = row >> 4, rho = row & 15;
    const int kb = col >> 4, kap = col & 15;
    return ((mb * KB16 + kb) * 32 + (rho & 7) * 4 + ((kap >> 1) & 3)) * 4 +
           (rho >> 3) + 2 * (kap >> 3);
}
// same for an h slab (8 kb blocks, 2 mb)
__device__ __forceinline__ int h2addr(int row, int col) {
    const int mb = row >> 4, rho = row & 15;
    const int kb = col >> 4, kap = col & 15;
    return ((mb * 8 + kb) * 32 + (rho & 7) * 4 + ((kap >> 1) & 3)) * 4 +
           (rho >> 3) + 2 * (kap >> 3);
}

__device__ __forceinline__ void gbar(int ncta, unsigned& sense) {
    __syncthreads();
    if (threadIdx.x == 0) {
        __threadfence();
        unsigned arrived = atomicAdd(&g_count, 1u) + 1u;
        if (arrived == (unsigned)ncta) {
            g_count = 0u;
            __threadfence();
            atomicAdd(&g_sense, 1u);
        } else {
            while ((int)(*(volatile unsigned*)&g_sense - (sense + 1u)) < 0) {
                __nanosleep(64);
            }
        }
    }
    sense += 1u;
    __syncthreads();
}

__global__ __launch_bounds__(512, 1) void spatial_gru_m2(
    const float* __restrict__ inputs, const float* __restrict__ Wr,
    const float* __restrict__ br, const float* __restrict__ Wz,
    const float* __restrict__ bz, const float* __restrict__ Wij,
    const float* __restrict__ bij, const float* __restrict__ WU,
    float* __restrict__ out, int ncta)
{
    extern __shared__ unsigned smem[];
    unsigned* qs = smem;
    unsigned* a2 = smem + QWH;
    unsigned* hmz = smem + HMZ0;   // [32 rows][132] zi/hmix half2
    const int tid = threadIdx.x;
    const int cta = blockIdx.x;
    const int gtid = cta * 512 + tid;
    const int gstride = ncta * 512;
    unsigned sense = *(volatile unsigned*)&g_sense;

    // ---------------- stage 0 -------------------------------------------
    if (gtid == 0) g_ticket = 0u;
    // pack weights -> fp16 fragments
    for (int idx = gtid; idx < 128 * KB16 * 32; idx += gstride) {
        const int lane = idx & 31;
        const int kb = (idx >> 5) % KB16;
        const int jblk = (idx >> 5) / KB16;
        const int jp = jblk * 8 + (lane >> 2);
        const int k = kb * 16 + (lane & 3) * 2;
        float w0, w1, w8, w9;
        if (jblk < 48) {
            const float* p = Wr + (size_t)jp * DD + k;
            w0 = p[0]; w1 = p[1]; w8 = p[8]; w9 = p[9];
        } else if (jblk < 112) {
            const int jz = jp - 384;
            const int j = (jz & 3) * 128 + (jz >> 2);
            const float* p = Wz + (size_t)j * DD + k;
            w0 = p[0]; w1 = p[1]; w8 = p[8]; w9 = p[9];
        } else {
            const int u = jp - 896;
            if (k < 384) {
                const float* p = WU + (size_t)u * 384 + k;
                w0 = p[0]; w1 = p[1]; w8 = p[8]; w9 = p[9];
            } else {
                const float* p = Wij + (size_t)u * 32 + (k - 384);
                w0 = p[0]; w1 = p[1]; w8 = p[8]; w9 = p[9];
            }
        }
        g_wph[jblk][kb][lane] = make_uint2(packh2(w0, w1), packh2(w8, w9));
    }
    // transpose inputs (B,C,L,R) -> fp16 (L,R,B,C)
    for (int idx = gtid; idx < BATCH * (CD / 2) * LDIM * (RDIM / 4); idx += gstride) {
        const int r4 = idx % (RDIM / 4);
        int t2 = idx / (RDIM / 4);
        const int l = t2 % LDIM; t2 /= LDIM;
        const int c2 = t2 & 15;
        const int b = t2 >> 4;
        const int c = c2 * 2, r0 = r4 * 4;
        const float* p0 = inputs + (((size_t)b * CD + c) * LDIM + l) * RDIM + r0;
        const float4 x0 = *(const float4*)p0;
        const float4 x1 = *(const float4*)(p0 + LDIM * RDIM);
        *(unsigned*)&g_sTh[l][r0 + 0][b][c] = packh2(x0.x, x1.x);
        *(unsigned*)&g_sTh[l][r0 + 1][b][c] = packh2(x0.y, x1.y);
        *(unsigned*)&g_sTh[l][r0 + 2][b][c] = packh2(x0.z, x1.z);
        *(unsigned*)&g_sTh[l][r0 + 3][b][c] = packh2(x0.w, x1.w);
    }
    for (int idx = gtid; idx < LDIM * RDIM * 4; idx += gstride)
        ((unsigned*)g_hflag)[idx] = 0u;
    gbar(ncta, sense);

    const int w = tid >> 5, lane = tid & 31;
    const int l4 = lane >> 2;

    // dynamic ticket walk state
    int dcur = 0;
    int dbase = 0;
    int nc = 1;   // nc(0) = 1

    int tkt = tid == 0 ? (int)atomicAdd(&g_ticket, 1u) : 0;
    __shared__ int s_tkt;
    for (;;) {
        if (tid == 0) s_tkt = tkt;
        __syncthreads();
        const int t = s_tkt;
        if (t >= NTASK) break;
        // prefetch NEXT ticket now (hides the L2 atomic behind the task body)
        if (tid == 0) tkt = (int)atomicAdd(&g_ticket, 1u);
        // advance diagonal pointer
        while (t >= dbase + 4 * nc) {
            dbase += 4 * nc;
            ++dcur;
            const int lo = (dcur > RDIM - 1) ? dcur - (RDIM - 1) : 0;
            const int hi = (dcur < LDIM - 1) ? dcur : LDIM - 1;
            nc = hi - lo + 1;
        }
        const int d = dcur;
        const int l0 = (d > RDIM - 1) ? d - (RDIM - 1) : 0;
        const int ti = t - dbase;
        const int ci = ti >> 2, qb = ti & 3;
        const int l = l0 + ci, rr = d - l;
        const int b0 = qb * 32;

        // -------- wait for neighbor h flags (acquire poll) --------
        if (tid < 3) {
            const unsigned* f = 0;
            if (tid == 0)      { if (rr > 0) f = &g_hflag[l][rr - 1][qb]; }
            else if (tid == 1) { if (l > 0)  f = &g_hflag[l - 1][rr][qb]; }
            else               { if (l > 0 && rr > 0) f = &g_hflag[l - 1][rr - 1][qb]; }
            if (f) {
                while (ld_acq(f) == 0u) { }
            }
        }
        __syncthreads();

        const uint4* ghtop  = (l > 0)  ? (const uint4*)&g_hhalf[l - 1][rr][qb][0] : (const uint4*)0;
        const uint4* ghleft = (rr > 0) ? (const uint4*)&g_hhalf[l][rr - 1][qb][0] : (const uint4*)0;
        const uint4* ghdiag = (l > 0 && rr > 0)
                             ? (const uint4*)&g_hhalf[l - 1][rr - 1][qb][0] : (const uint4*)0;

        // -------- build q: h regions are direct fragment copies --------
        for (int idx = tid; idx < 1536; idx += 512) {
            const int ln = idx & 31;
            const int kq = (idx >> 5) % 24;
            const int mb = (idx >> 5) / 24;
            const uint4* src;
            if (kq < 8)       src = ghtop;
            else if (kq < 16) src = ghleft;
            else              src = ghdiag;
            uint4 v = make_uint4(0u, 0u, 0u, 0u);
            if (src) v = src[(mb * 8 + (kq & 7)) * 32 + ln];
            *(uint4*)(qs + ((mb * KB16 + kq) * 32 + ln) * 4) = v;
        }
        // s region (q kb 24,25) — GEMM2 reads these from q directly (no copy)
        if (tid < 128) {
            const int ln = tid & 31;
            const int kb2 = (tid >> 5) & 1;
            const int mb = tid >> 6;
            const int row = b0 + mb * 16 + (ln >> 2);
            const int c0 = kb2 * 16 + (ln & 3) * 2;
            const __half* s0 = &g_sTh[l][rr][row][0];
            const __half* s1 = &g_sTh[l][rr][row + 8][0];
            uint4 v;
            v.x = *(const unsigned*)(s0 + c0);
            v.y = *(const unsigned*)(s1 + c0);
            v.z = *(const unsigned*)(s0 + c0 + 8);
            v.w = *(const unsigned*)(s1 + c0 + 8);
            *(uint4*)(qs + ((mb * KB16 + 24 + kb2) * 32 + ln) * 4) = v;
        }
        __syncthreads();

        // ======= merged GEMM1 (r: 3 jblks, z: 4 jblks) x 2 m-blocks =======
        float accr[2][3][4];
        float accz[2][4][4];
        {
#pragma unroll
            for (int mt = 0; mt < 2; ++mt) {
#pragma unroll
                for (int nt = 0; nt < 3; ++nt)
#pragma unroll
                    for (int i = 0; i < 4; ++i) accr[mt][nt][i] = 0.f;
#pragma unroll
                for (int nt = 0; nt < 4; ++nt)
#pragma unroll
                    for (int i = 0; i < 4; ++i) accz[mt][nt][i] = 0.f;
            }
            const uint2* wp[7];
#pragma unroll
            for (int j = 0; j < 7; ++j) {
                const int jblk = (j < 3) ? (j * 16 + w) : (48 + (j - 3) * 16 + w);
                wp[j] = &g_wph[jblk][0][lane];
            }
            uint2 wb[2][7];
#pragma unroll
            for (int j = 0; j < 7; ++j) {
                wb[0][j] = wp[j][0];
                wb[1][j] = wp[j][32];
            }
#pragma unroll 2
            for (int kb = 0; kb < KB16; ++kb) {
                const int par = kb & 1;
                uint4 av[2];
#pragma unroll
                for (int mt = 0; mt < 2; ++mt)
                    av[mt] = *(const uint4*)(qs + ((mt * KB16 + kb) * 32 + lane) * 4);
#pragma unroll
                for (int mt = 0; mt < 2; ++mt) {
#pragma unroll
                    for (int nt = 0; nt < 3; ++nt)
                        mma16(accr[mt][nt], av[mt], wb[par][nt]);
#pragma unroll
                    for (int nt = 0; nt < 4; ++nt)
                        mma16(accz[mt][nt], av[mt], wb[par][3 + nt]);
                }
#pragma unroll
                for (int j = 0; j < 7; ++j)
                    wb[par][j] = wp[j][(kb + 2) * 32];
            }
        }

        // -------- r-epilogue: a2 = sigmoid(r + br) * h --------
#pragma unroll
        for (int nt = 0; nt < 3; ++nt) {
            const int jblk = nt * 16 + w;
            const int col0 = jblk * 8 + (lane & 3) * 2;
            const float b0r = br[col0], b1r = br[col0 + 1];
            const int qc0 = (col0 < 128) ? col0 + 128
                          : (col0 < 256) ? col0 - 128 : col0;
#pragma unroll
            for (int mt = 0; mt < 2; ++mt) {
#pragma unroll
                for (int rs = 0; rs < 2; ++rs) {
                    const int rowl = mt * 16 + l4 + rs * 8;
                    const unsigned hv = qs[q2addr(rowl, qc0)];
                    const __half2 hh = *(const __half2*)&hv;
                    const float p0 = accr[mt][nt][rs * 2 + 0] + b0r;
                    const float p1 = accr[mt][nt][rs * 2 + 1] + b1r;
                    const float v0 = __low2float(hh) * fast_sig(p0);
                    const float v1 = __high2float(hh) * fast_sig(p1);
                    a2[q2addr(rowl, col0)] = packh2(v0, v1);
                }
            }
        }

        // -------- z-epilogue: register softmax (partner lane^1), write hmz -
        {
            const __half* qh = (const __half*)qs;
#pragma unroll
            for (int nt = 0; nt < 4; ++nt) {
                const int jblk = 48 + nt * 16 + w;
                const int pcol = (jblk - 48) * 8 + (lane & 3) * 2;
                const int u = pcol >> 2;
                const int gb = pcol & 3;
                const bool ev = (gb == 0);
                const float bz0 = bz[gb * 128 + u];
                const float bz1 = bz[(gb + 1) * 128 + u];
#pragma unroll
                for (int mt = 0; mt < 2; ++mt) {
#pragma unroll
                    for (int rs = 0; rs < 2; ++rs) {
                        const int row = mt * 16 + l4 + rs * 8;
                        const float v0 = accz[mt][nt][rs * 2 + 0] + bz0;
                        const float v1 = accz[mt][nt][rs * 2 + 1] + bz1;
                        float m = fmaxf(v0, v1);
                        m = fmaxf(m, __shfl_xor_sync(0xffffffffu, m, 1));
                        const float e0 = __expf(v0 - m), e1 = __expf(v1 - m);
                        float s = e0 + e1;
                        s += __shfl_xor_sync(0xffffffffu, s, 1);
                        const float inv = __fdividef(1.f, s);
                        float part;
                        if (ev) {
                            const int c = 128 + u;
                            const float hlv = __half2float(
                                qh[q2addr(row, c & ~1) * 2 + (c & 1)]);
                            part = e1 * hlv;
                        } else {
                            const float htv = __half2float(
                                qh[q2addr(row, u & ~1) * 2 + (u & 1)]);
                            const int c = 256 + u;
                            const float hdv = __half2float(
                                qh[q2addr(row, c & ~1) * 2 + (c & 1)]);
                            part = e0 * htv + e1 * hdv;
                        }
                        const float hm = (part + __shfl_xor_sync(0xffffffffu, part, 1)) * inv;
                        if (ev)
                            hmz[row * 132 + u] = packh2(e0 * inv, hm);
                    }
                }
            }
        }
        __syncthreads();   // a2 + hmz ready; q (incl. s kbs) still intact

        // ================= GEMM2: 1 jblk x 2 m-blocks per warp ===========
        {
            const int jb = 112 + w;
            float acc2[2][4];
#pragma unroll
            for (int mt = 0; mt < 2; ++mt)
#pragma unroll
                for (int i = 0; i < 4; ++i) acc2[mt][i] = 0.f;
            uint2 wb2[2];
            wb2[0] = g_wph[jb][0][lane];
            wb2[1] = g_wph[jb][1][lane];
#pragma unroll 2
            for (int kb = 0; kb < KB16; ++kb) {
                const int par = kb & 1;
                const unsigned* abase = (kb < 24) ? a2 : qs;   // s kbs live in q
                uint4 av[2];
#pragma unroll
                for (int mt = 0; mt < 2; ++mt)
                    av[mt] = *(const uint4*)(abase + ((mt * KB16 + kb) * 32 + lane) * 4);
#pragma unroll
                for (int mt = 0; mt < 2; ++mt)
                    mma16(acc2[mt], av[mt], wb2[par]);
                wb2[par] = g_wph[jb][kb + 2][lane];
            }
            // h = hmix + zi * tanh(ghat + bij); write fragment h slab
            unsigned* ghout = &g_hhalf[l][rr][qb][0];
            const int u0 = w * 8 + (lane & 3) * 2;
            const float2 bj = *(const float2*)(bij + u0);
#pragma unroll
            for (int mt = 0; mt < 2; ++mt) {
#pragma unroll
                for (int rs = 0; rs < 2; ++rs) {
                    const int rowl = mt * 16 + l4 + rs * 8;
                    const unsigned m0 = hmz[rowl * 132 + u0];
                    const unsigned m1 = hmz[rowl * 132 + u0 + 1];
                    const __half2 z0 = *(const __half2*)&m0;
                    const __half2 z1 = *(const __half2*)&m1;
                    const float h0 = __high2float(z0) + __low2float(z0) *
                        fast_tanh(acc2[mt][rs * 2 + 0] + bj.x);
                    const float h1 = __high2float(z1) + __low2float(z1) *
                        fast_tanh(acc2[mt][rs * 2 + 1] + bj.y);
                    __stcg(ghout + h2addr(rowl, u0), packh2(h0, h1));
                    if (d == NDIAG - 1)
                        *(float2*)(out + (size_t)(b0 + rowl) * UD + u0) =
                            make_float2(h0, h1);
                }
            }
        }
        __syncthreads();
        if (tid == 0) st_rel(&g_hflag[l][rr][qb], 1u);
    }
}

// ---------------------------------------------------------------------------
extern "C" void kernel_launch(void* const* d_in, const int* in_sizes, int n_in,
                              void* d_out, int out_size)
{
    const float* inputs = (const float*)d_in[0];
    const float* Wr     = (const float*)d_in[1];
    const float* br     = (const float*)d_in[2];
    const float* Wz     = (const float*)d_in[3];
    const float* bz     = (const float*)d_in[4];
    const float* Wij    = (const float*)d_in[5];
    const float* bij    = (const float*)d_in[6];
    const float* WU     = (const float*)d_in[7];
    float* out = (float*)d_out;

    const int SMEM = (2 * QWH + 32 * 132) * (int)sizeof(unsigned);  // 123392 B
    cudaFuncSetAttribute(spatial_gru_m2,
                         cudaFuncAttributeMaxDynamicSharedMemorySize, SMEM);
    int dev = 0;
    cudaGetDevice(&dev);
    int nsm = 0;
    cudaDeviceGetAttribute(&nsm, cudaDevAttrMultiProcessorCount, dev);
    const int ncta = nsm;   // 1 CTA/SM; grid == resident CTAs (deadlock-free)

    spatial_gru_m2<<<ncta, 512, SMEM>>>(inputs, Wr, br, Wz, bz, Wij, bij,
                                        WU, out, ncta);
}